// round 11
// baseline (speedup 1.0000x reference)
#include <cuda_runtime.h>
#include <cuda_fp16.h>
#include <cstdint>

// Problem constants
#define BB 16
#define LL 256
#define DD 512
#define MELS 80
#define TF 3072
#define M2 (BB * TF)
#define MEL_ELEMS (BB * MELS * TF)
#define KC_N (DD / 32)        // 16 K-chunks of 32
#define FRAG_W 2048           // fp16 fragment block: 128n x 32k = 8 KB (words)

// Scratch (device globals; no allocations allowed)
__device__ unsigned g_xh[BB * LL * (DD / 2)];      // embed+pos, fp16x2
__device__ unsigned g_ench[BB * LL * (DD / 2)];    // encoder out fp16x2
__device__ unsigned g_dech[(size_t)M2 * (DD / 2)]; // decoder out fp16x2
__device__ int      g_tok[M2];                     // frame -> token (-1 invalid)
__device__ int      g_csum[BB * LL];               // per-batch duration cumsum
__device__ float    g_durp[BB * LL * 16];          // dur-head partials [row][ntile*4+wn]
__device__ unsigned g_WencF[4 * KC_N * FRAG_W];    // fragment-order fp16 weights
__device__ unsigned g_WdecF[4 * KC_N * FRAG_W];
__device__ unsigned g_WgenF[1 * KC_N * FRAG_W];    // n>=80 zero-padded
__device__ float    g_cvec[MELS];                  // relu(b_dec) @ W_gen + b_gen

__device__ __forceinline__ unsigned pkh2(float lo, float hi) {
    __half2 h = __floats2half2_rn(lo, hi);
    return *(unsigned*)&h;
}
__device__ __forceinline__ void mma16f(float c[4], const unsigned a[4], const unsigned b[2]) {
    asm volatile(
        "mma.sync.aligned.m16n8k16.row.col.f32.f16.f16.f32 "
        "{%0,%1,%2,%3}, {%4,%5,%6,%7}, {%8,%9}, {%0,%1,%2,%3};"
        : "+f"(c[0]), "+f"(c[1]), "+f"(c[2]), "+f"(c[3])
        : "r"(a[0]), "r"(a[1]), "r"(a[2]), "r"(a[3]), "r"(b[0]), "r"(b[1]));
}
__device__ __forceinline__ void ldmx4(unsigned r[4], unsigned saddr) {
    asm volatile("ldmatrix.sync.aligned.m8n8.x4.shared.b16 {%0,%1,%2,%3}, [%4];"
                 : "=r"(r[0]), "=r"(r[1]), "=r"(r[2]), "=r"(r[3]) : "r"(saddr));
}
__device__ __forceinline__ void cp16(unsigned dst, const void* src, unsigned sz) {
    asm volatile("cp.async.cg.shared.global [%0], [%1], 16, %2;"
                 :: "r"(dst), "l"(src), "r"(sz));
}
__device__ __forceinline__ void cp_commit() {
    asm volatile("cp.async.commit_group;" ::: "memory");
}
template <int N>
__device__ __forceinline__ void cp_wait() {
    asm volatile("cp.async.wait_group %0;" :: "n"(N) : "memory");
}

// ---------------------------------------------------------------------------
// Fused prologue: fragment-order weights (blocks 0..143), cvec (144..223),
// embed+pos -> fp16 (224..2271).
__device__ __forceinline__ void wfrag_block(const float* __restrict__ W,
                                            unsigned* __restrict__ out,
                                            int ntile, int kc, int Ncols) {
    for (int w = threadIdx.x; w < FRAG_W; w += 256) {
        int r = w & 1, lane = (w >> 1) & 31, ks = (w >> 6) & 1, nt = w >> 7;
        int n = ntile * 128 + nt * 8 + (lane >> 2);
        int k = kc * 32 + ks * 16 + 2 * (lane & 3) + 8 * r;
        float lo = 0.f, hi = 0.f;
        if (n < Ncols) {
            lo = W[(size_t)k * Ncols + n];
            hi = W[(size_t)(k + 1) * Ncols + n];
        }
        out[w] = pkh2(lo, hi);
    }
}
__global__ void prep_kernel(const float* __restrict__ W_enc,
                            const float* __restrict__ W_dec,
                            const float* __restrict__ W_gen,
                            const float* __restrict__ b_dec,
                            const float* __restrict__ b_gen,
                            const int* __restrict__ src,
                            const float* __restrict__ emb,
                            const float* __restrict__ pos) {
    int blk = blockIdx.x;
    int tid = threadIdx.x;
    if (blk < 144) {
        if (blk < 64)
            wfrag_block(W_enc, g_WencF + (size_t)blk * FRAG_W, blk / KC_N, blk % KC_N, DD);
        else if (blk < 128) {
            int b2 = blk - 64;
            wfrag_block(W_dec, g_WdecF + (size_t)b2 * FRAG_W, b2 / KC_N, b2 % KC_N, DD);
        } else {
            int b3 = blk - 128;
            wfrag_block(W_gen, g_WgenF + (size_t)b3 * FRAG_W, 0, b3 % KC_N, MELS);
        }
    } else if (blk < 224) {
        int m = blk - 144;
        float acc = 0.0f;
        for (int k = tid; k < DD; k += 256)
            acc += fmaxf(b_dec[k], 0.0f) * W_gen[k * MELS + m];
        #pragma unroll
        for (int o = 16; o; o >>= 1) acc += __shfl_down_sync(0xffffffffu, acc, o);
        __shared__ float s[8];
        if ((tid & 31) == 0) s[tid >> 5] = acc;
        __syncthreads();
        if (tid == 0) {
            float t = b_gen[m];
            #pragma unroll
            for (int i = 0; i < 8; i++) t += s[i];
            g_cvec[m] = t;
        }
    } else {
        int idx = blk - 224;                 // 0..2047, 2 rows each
        int row = idx * 2 + (tid >> 7);
        int l = row & (LL - 1);
        int v = src[row];
        int d = (tid & 127) * 4;
        float4 e = *(const float4*)(emb + (size_t)v * DD + d);
        float4 p = *(const float4*)(pos + (size_t)l * DD + d);
        *(uint2*)(g_xh + (size_t)row * (DD / 2) + (tid & 127) * 2) =
            make_uint2(pkh2(e.x + p.x, e.y + p.y), pkh2(e.z + p.z, e.w + p.w));
    }
}

// ---------------------------------------------------------------------------
// Token map, two stages: per-batch scan then parallel searchsorted fill.
__global__ void tok_scan(const int* __restrict__ dur) {
    int b = blockIdx.x;
    __shared__ int cs[LL];
    int l = threadIdx.x;
    cs[l] = dur[b * LL + l];
    __syncthreads();
    for (int off = 1; off < LL; off <<= 1) {
        int v = (l >= off) ? cs[l - off] : 0;
        __syncthreads();
        cs[l] += v;
        __syncthreads();
    }
    g_csum[b * LL + l] = cs[l];
}
__global__ void tok_fill() {
    int b = blockIdx.x;
    int t = blockIdx.y * 256 + threadIdx.x;
    __shared__ int cs[LL];
    cs[threadIdx.x] = g_csum[b * LL + threadIdx.x];
    __syncthreads();
    int lo = 0, hi = LL;
    while (lo < hi) {
        int mid = (lo + hi) >> 1;
        if (cs[mid] <= t) lo = mid + 1; else hi = mid;
    }
    g_tok[b * TF + t] = (lo < LL) ? lo : -1;
}

// dur finalize: sum 16 partials + b_dur
__global__ void dur_fin(const float* __restrict__ b_dur, float* __restrict__ out) {
    int row = blockIdx.x * 256 + threadIdx.x;   // 0..4095
    float s = b_dur[0];
    const float* p = g_durp + (size_t)row * 16;
    #pragma unroll
    for (int i = 0; i < 16; i++) s += p[i];
    out[row] = s;
}

// ---------------------------------------------------------------------------
// fp16 mma.sync GEMM (m16n8k16), CTA 128x128, 8 warps (2m x 4n), warp 64x32.
// 4-stage cp.async pipeline; A via ldmatrix.x4; B precomputed fragments.
// __launch_bounds__(256, 2): 2 CTAs/SM for cross-CTA latency hiding.
// MODE 0 = enc (A=g_xh; out fp16 g_ench + dur-head partials)
// MODE 1 = dec (A=gather(g_ench) w/ zfill; skip invalid tiles; out fp16)
// MODE 2 = gen (A=g_dech; N=80; transposed mel; invalid tiles -> cvec)
#define A_P2 20                         // words per A row (40 halfs, 4 pad)
#define A_BY (128 * A_P2 * 4)           // 10240
#define B_BY (FRAG_W * 4)               // 8192
#define STG_BY (A_BY + B_BY)            // 18432
#define N_STG 4
#define SMEM_SZ (N_STG * STG_BY)        // 73728 (>= GEN sC 40960)

template <int MODE>
__global__ __launch_bounds__(256, 2)
void mma_gemm(const unsigned* __restrict__ Ain, const unsigned* __restrict__ WF,
              const float* __restrict__ bias, void* __restrict__ Cout,
              const float* __restrict__ Wdur) {
    extern __shared__ unsigned char sraw[];
    const int tid = threadIdx.x;
    const int lane = tid & 31, wid = tid >> 5;
    const int wm = wid & 1, wn = wid >> 1;
    const int g = lane >> 2, ct = lane & 3;
    const int r0 = blockIdx.y * 128;
    const int ntile = (MODE == 2) ? 0 : blockIdx.x;

    int bb = 0, t0 = 0;
    if (MODE == 2) {
        bb = r0 / TF; t0 = r0 % TF;
        if (g_tok[r0] < 0) {
            float* mp = (float*)Cout + (size_t)bb * MELS * TF + t0;
            for (int idx = tid; idx < MELS * 128; idx += 256) {
                int m = idx >> 7, f = idx & 127;
                mp[(size_t)m * TF + f] = g_cvec[m];
            }
            return;
        }
    }
    if (MODE == 1 && g_tok[r0] < 0) return;

    const unsigned sbase = (unsigned)__cvta_generic_to_shared(sraw);

    // cp.async source/dest mapping: thread pair per A row; B contiguous copy
    const int srow = tid >> 1, half = tid & 1;
    const unsigned* arow;
    unsigned asz = 16;
    if (MODE == 1) {
        int r = r0 + srow;
        int tk = g_tok[r];
        if (tk >= 0) arow = g_ench + ((size_t)(r / TF) * LL + tk) * (DD / 2);
        else { arow = g_ench; asz = 0; }           // zero-fill row
    } else {
        arow = Ain + (size_t)(r0 + srow) * (DD / 2);
    }
    arow += half * 8;
    const unsigned adst = (srow * A_P2 + half * 8) * 4;
    const unsigned* bsrc0 = WF + (size_t)ntile * KC_N * FRAG_W + tid * 8;
    const unsigned bdst = A_BY + tid * 32;

    // ldmatrix lane addressing for A fragments
    const int lm = lane >> 3, rr = lane & 7;
    unsigned arow_w[4];
    #pragma unroll
    for (int mt = 0; mt < 4; mt++)
        arow_w[mt] = (unsigned)((wm * 64 + mt * 16 + (lm & 1) * 8 + rr) * A_P2 +
                                (lm >> 1) * 4);

    float c[4][4][4];
    #pragma unroll
    for (int mt = 0; mt < 4; mt++)
        #pragma unroll
        for (int nt = 0; nt < 4; nt++)
            #pragma unroll
            for (int j = 0; j < 4; j++) c[mt][nt][j] = 0.0f;

    #define ISSUE(kc, s)                                                   \
        do {                                                               \
            unsigned st = sbase + (s) * STG_BY;                            \
            cp16(st + adst, arow + (kc) * 16, asz);                        \
            cp16(st + adst + 16, arow + (kc) * 16 + 4, asz);               \
            const unsigned* bp = bsrc0 + (size_t)(kc) * FRAG_W;            \
            cp16(st + bdst, bp, 16);                                       \
            cp16(st + bdst + 16, bp + 4, 16);                              \
            cp_commit();                                                   \
        } while (0)

    #define COMPUTE(s)                                                    \
        do {                                                              \
            unsigned ab = sbase + (s) * STG_BY;                           \
            const uint2* Bp = (const uint2*)(sraw + (s) * STG_BY + A_BY); \
            _Pragma("unroll")                                             \
            for (int ks = 0; ks < 2; ks++) {                              \
                unsigned af[4][4], bf[4][2];                              \
                _Pragma("unroll")                                         \
                for (int mt = 0; mt < 4; mt++)                            \
                    ldmx4(af[mt], ab + (arow_w[mt] + ks * 8) * 4);        \
                _Pragma("unroll")                                         \
                for (int nt = 0; nt < 4; nt++)                            \
                    *(uint2*)bf[nt] =                                     \
                        Bp[((wn * 4 + nt) * 2 + ks) * 32 + lane];         \
                _Pragma("unroll")                                         \
                for (int mt = 0; mt < 4; mt++)                            \
                    _Pragma("unroll")                                     \
                    for (int nt = 0; nt < 4; nt++)                        \
                        mma16f(c[mt][nt], af[mt], bf[nt]);                \
            }                                                             \
        } while (0)

    ISSUE(0, 0);
    ISSUE(1, 1);
    ISSUE(2, 2);
    #pragma unroll 4
    for (int kc = 0; kc < KC_N; kc++) {
        if (kc + 3 < KC_N) cp_wait<2>(); else cp_wait<0>();
        __syncthreads();
        COMPUTE(kc % N_STG);
        if (kc + 3 < KC_N) ISSUE(kc + 3, (kc + 3) % N_STG);
    }
    #undef ISSUE
    #undef COMPUTE

    if (MODE == 2) {
        __syncthreads();
        float* sC = (float*)sraw;  // [80][128] = 40 KB
        #pragma unroll
        for (int mt = 0; mt < 4; mt++) {
            int f0 = wm * 64 + mt * 16 + g;
            #pragma unroll
            for (int nt = 0; nt < 4; nt++) {
                int n = wn * 32 + nt * 8 + ct * 2;
                if (n < MELS) {
                    sC[n * 128 + f0]           = c[mt][nt][0];
                    sC[(n + 1) * 128 + f0]     = c[mt][nt][1];
                    sC[n * 128 + f0 + 8]       = c[mt][nt][2];
                    sC[(n + 1) * 128 + f0 + 8] = c[mt][nt][3];
                }
            }
        }
        __syncthreads();
        float* mp = (float*)Cout + (size_t)bb * MELS * TF + t0;
        #pragma unroll
        for (int i = 0; i < 10; i++) {
            int flat = tid + i * 256;
            int m = flat >> 5, q = flat & 31;
            float4 v = *(float4*)(sC + m * 128 + q * 4);
            float bm = __ldg(bias + m);
            v.x += bm; v.y += bm; v.z += bm; v.w += bm;
            *(float4*)(mp + (size_t)m * TF + q * 4) = v;
        }
    } else if (MODE == 1) {
        unsigned* Ch = (unsigned*)Cout;
        #pragma unroll
        for (int mt = 0; mt < 4; mt++) {
            int row0 = r0 + wm * 64 + mt * 16 + g;
            unsigned* C0 = Ch + (size_t)row0 * (DD / 2);
            unsigned* C1 = C0 + (size_t)8 * (DD / 2);
            #pragma unroll
            for (int nt = 0; nt < 4; nt++) {
                int n = ntile * 128 + wn * 32 + nt * 8 + ct * 2;
                float b0 = __ldg(bias + n), b1 = __ldg(bias + n + 1);
                C0[n >> 1] = pkh2(fmaxf(c[mt][nt][0] + b0, 0.f),
                                  fmaxf(c[mt][nt][1] + b1, 0.f));
                C1[n >> 1] = pkh2(fmaxf(c[mt][nt][2] + b0, 0.f),
                                  fmaxf(c[mt][nt][3] + b1, 0.f));
            }
        }
    } else {
        // enc: relu -> fp16 out + duration-head partials (fp32, deterministic)
        unsigned* Ch = (unsigned*)Cout;
        #pragma unroll
        for (int mt = 0; mt < 4; mt++) {
            int row0 = r0 + wm * 64 + mt * 16 + g;
            unsigned* C0 = Ch + (size_t)row0 * (DD / 2);
            unsigned* C1 = C0 + (size_t)8 * (DD / 2);
            float dp0 = 0.f, dp1 = 0.f;
            #pragma unroll
            for (int nt = 0; nt < 4; nt++) {
                int n = ntile * 128 + wn * 32 + nt * 8 + ct * 2;
                float b0 = __ldg(bias + n), b1 = __ldg(bias + n + 1);
                float v0 = fmaxf(c[mt][nt][0] + b0, 0.f);
                float v1 = fmaxf(c[mt][nt][1] + b1, 0.f);
                float v2 = fmaxf(c[mt][nt][2] + b0, 0.f);
                float v3 = fmaxf(c[mt][nt][3] + b1, 0.f);
                C0[n >> 1] = pkh2(v0, v1);
                C1[n >> 1] = pkh2(v2, v3);
                float w0 = __ldg(Wdur + n), w1 = __ldg(Wdur + n + 1);
                dp0 += v0 * w0 + v1 * w1;
                dp1 += v2 * w0 + v3 * w1;
            }
            dp0 += __shfl_xor_sync(0xffffffffu, dp0, 1);
            dp0 += __shfl_xor_sync(0xffffffffu, dp0, 2);
            dp1 += __shfl_xor_sync(0xffffffffu, dp1, 1);
            dp1 += __shfl_xor_sync(0xffffffffu, dp1, 2);
            if (ct == 0) {
                g_durp[(size_t)row0 * 16 + ntile * 4 + wn] = dp0;
                g_durp[(size_t)(row0 + 8) * 16 + ntile * 4 + wn] = dp1;
            }
        }
    }
}

// ---------------------------------------------------------------------------
extern "C" void kernel_launch(void* const* d_in, const int* in_sizes, int n_in,
                              void* d_out, int out_size) {
    const int*   src   = (const int*)d_in[0];
    const int*   durin = (const int*)d_in[1];
    const float* emb   = (const float*)d_in[3];
    const float* pos   = (const float*)d_in[4];
    const float* W_enc = (const float*)d_in[5];
    const float* b_enc = (const float*)d_in[6];
    const float* W_dur = (const float*)d_in[7];
    const float* b_dur = (const float*)d_in[8];
    const float* W_dec = (const float*)d_in[9];
    const float* b_dec = (const float*)d_in[10];
    const float* W_gen = (const float*)d_in[11];
    const float* b_gen = (const float*)d_in[12];

    float* out     = (float*)d_out;
    float* mel     = out;
    float* dur_out = out + MEL_ELEMS;

    unsigned* gxh;  cudaGetSymbolAddress((void**)&gxh,  g_xh);
    unsigned* geh;  cudaGetSymbolAddress((void**)&geh,  g_ench);
    unsigned* gdh;  cudaGetSymbolAddress((void**)&gdh,  g_dech);
    unsigned* wef;  cudaGetSymbolAddress((void**)&wef,  g_WencF);
    unsigned* wdf;  cudaGetSymbolAddress((void**)&wdf,  g_WdecF);
    unsigned* wgf;  cudaGetSymbolAddress((void**)&wgf,  g_WgenF);

    cudaFuncSetAttribute(mma_gemm<0>, cudaFuncAttributeMaxDynamicSharedMemorySize, SMEM_SZ);
    cudaFuncSetAttribute(mma_gemm<1>, cudaFuncAttributeMaxDynamicSharedMemorySize, SMEM_SZ);
    cudaFuncSetAttribute(mma_gemm<2>, cudaFuncAttributeMaxDynamicSharedMemorySize, SMEM_SZ);

    // prologue (weights, cvec, embed) + token map
    prep_kernel<<<2272, 256>>>(W_enc, W_dec, W_gen, b_dec, b_gen, src, emb, pos);
    tok_scan<<<BB, LL>>>(durin);
    tok_fill<<<dim3(BB, TF / 256), 256>>>();

    // enc = relu(x @ W_enc + b_enc) -> fp16 + dur partials
    mma_gemm<0><<<dim3(4, (BB * LL) / 128), 256, SMEM_SZ>>>(gxh, wef, b_enc, geh, W_dur);

    // dur_pred = partials sum + b_dur
    dur_fin<<<BB * LL / 256, 256>>>(b_dur, dur_out);

    // dec = relu(gather(enc) @ W_dec + b_dec) -> fp16, valid tiles only
    mma_gemm<1><<<dim3(4, M2 / 128), 256, SMEM_SZ>>>(geh, wdf, b_dec, gdh, nullptr);

    // mel = transpose(dec @ W_gen + b_gen); invalid tiles -> cvec
    mma_gemm<2><<<dim3(1, M2 / 128), 256, SMEM_SZ>>>(gdh, wgf, b_gen, mel, nullptr);
}